// round 1
// baseline (speedup 1.0000x reference)
#include <cuda_runtime.h>

#define NB 1024
#define LD 32
#define HD 64
#define EPSV 1e-6f
#define SELF_SCALE 0.5f
#define INT_SCALE 0.3f

// Scratch (device globals; no allocation allowed in kernel_launch)
__device__ __align__(16) float g_A[NB * HD];     // a_i
__device__ __align__(16) float g_Bv[NB * HD];    // b_j (incl. bi1)
__device__ __align__(16) float g_CI[NB * LD];    // h @ Wc[:, :L].T
__device__ __align__(16) float g_CJ[NB * LD];    // h @ Wc[:, L:].T
__device__ __align__(16) float g_SELF[NB * LD];  // self_term
__device__ __align__(16) float g_Hh[NB * LD];    // packed h rows
__device__ float g_AG[NB];                       // sigmoid(aggr)
__device__ float g_PH[NB];                       // phases

__device__ __forceinline__ float tanh_fast(float x) {
    // 1 - 2/(exp(2x)+1): exact at both saturation ends, ~1e-7 rel err
    float e = __expf(2.0f * x);
    return 1.0f - __fdividef(2.0f, e + 1.0f);
}

// ---------------------------------------------------------------------------
// Phase 1: per-node precompute. One block (64 threads) per node i.
// ---------------------------------------------------------------------------
__global__ void phase1_kernel(
    const float* __restrict__ state,
    const float* __restrict__ Ws1, const float* __restrict__ bs1,
    const float* __restrict__ Ws2, const float* __restrict__ bs2,
    const float* __restrict__ Ws3, const float* __restrict__ bs3,
    const float* __restrict__ Wi1, const float* __restrict__ bi1,
    const float* __restrict__ Wc,  const float* __restrict__ aggr)
{
    int i = blockIdx.x;
    int t = threadIdx.x;  // 0..63

    __shared__ float sh[LD], st1[HD], st2[HD], sdh[LD];

    if (t < LD) sh[t] = state[i * (LD + 1) + t];
    __syncthreads();

    // layer 1: tanh(h @ Ws1.T + bs1)
    float acc = bs1[t];
#pragma unroll
    for (int l = 0; l < LD; l++) acc += Ws1[t * LD + l] * sh[l];
    st1[t] = tanhf(acc);
    __syncthreads();

    // layer 2
    acc = bs2[t];
#pragma unroll
    for (int k = 0; k < HD; k++) acc += Ws2[t * HD + k] * st1[k];
    st2[t] = tanhf(acc);
    __syncthreads();

    // layer 3 (self term = dh)
    if (t < LD) {
        acc = bs3[t];
#pragma unroll
        for (int k = 0; k < HD; k++) acc += Ws3[t * HD + k] * st2[k];
        sdh[t] = acc;
        g_SELF[i * LD + t] = acc;
        g_Hh[i * LD + t] = sh[t];
    }
    __syncthreads();

    // a_i = h@Wi1[:, :L].T + dh@Wi1[:, 2L:3L].T
    // b_i = h@Wi1[:, L:2L].T + dh@Wi1[:, 3L:].T + bi1
    float a = 0.0f, b = bi1[t];
#pragma unroll
    for (int l = 0; l < LD; l++) {
        float hv = sh[l], dv = sdh[l];
        const float* row = Wi1 + t * (4 * LD);
        a += row[l] * hv + row[2 * LD + l] * dv;
        b += row[LD + l] * hv + row[3 * LD + l] * dv;
    }
    g_A[i * HD + t] = a;
    g_Bv[i * HD + t] = b;

    if (t < LD) {
        float ci = 0.0f, cj = 0.0f;
#pragma unroll
        for (int m = 0; m < LD; m++) {
            ci += Wc[t * (2 * LD) + m] * sh[m];
            cj += Wc[t * (2 * LD) + LD + m] * sh[m];
        }
        g_CI[i * LD + t] = ci;
        g_CJ[i * LD + t] = cj;
    }
    if (t == 0) {
        g_AG[i] = 1.0f / (1.0f + expf(-aggr[i]));
        g_PH[i] = state[i * (LD + 1) + LD];
    }
}

// ---------------------------------------------------------------------------
// Phase 2: pairwise interaction + reduction. One block (128 threads) per i.
// Each thread handles j = tid, tid+128, ... (8 j's), full per-pair pipeline.
// ---------------------------------------------------------------------------
__global__ void __launch_bounds__(128) phase2_kernel(
    const float* __restrict__ Wi2, const float* __restrict__ bi2,
    const float* __restrict__ Wi3, const float* __restrict__ bi3,
    const float* __restrict__ phase_w, const float* __restrict__ bc,
    float* __restrict__ out)
{
    __shared__ __align__(16) float sWi2[HD * HD];    // 16 KB
    __shared__ __align__(16) float sWi3T[HD * LD];   // 8 KB, transposed: [r][l]
    __shared__ float sA[HD], sBi2[HD];
    __shared__ float sHi[LD], sCi[LD], sBi3[LD], sPw[LD], sBc[LD];
    __shared__ float red[128 * 33];                  // pad 33 -> conflict-free

    int i = blockIdx.x;
    int tid = threadIdx.x;

    for (int k = tid; k < HD * HD; k += 128) sWi2[k] = Wi2[k];
    for (int k = tid; k < HD * LD; k += 128) {
        int r = k >> 5, l = k & 31;
        sWi3T[r * LD + l] = Wi3[l * HD + r];
    }
    if (tid < HD) { sA[tid] = g_A[i * HD + tid]; sBi2[tid] = bi2[tid]; }
    if (tid < LD) {
        sHi[tid] = g_Hh[i * LD + tid];
        sCi[tid] = g_CI[i * LD + tid];
        sBi3[tid] = bi3[tid];
        sPw[tid] = phase_w[tid];
        sBc[tid] = bc[tid];
    }
    __syncthreads();

    float agg_i = g_AG[i];
    float ph_i = g_PH[i];

    float isum[LD];
#pragma unroll
    for (int l = 0; l < LD; l++) isum[l] = 0.0f;

    for (int j = tid; j < NB; j += 128) {
        if (j == i) continue;

        // ---- distance & scale factor (stream h_j, don't hold it) ----
        const float4* hjp = (const float4*)(g_Hh + j * LD);
        float d2 = 0.0f;
#pragma unroll
        for (int q = 0; q < 8; q++) {
            float4 v = hjp[q];
            float e0 = sHi[4 * q + 0] - v.x;
            float e1 = sHi[4 * q + 1] - v.y;
            float e2 = sHi[4 * q + 2] - v.z;
            float e3 = sHi[4 * q + 3] - v.w;
            d2 += e0 * e0 + e1 * e1 + e2 * e2 + e3 * e3;
        }
        float dist = sqrtf(d2) + EPSV;
        float s = fminf(__fdividef(1.0f, dist), 2.0f) * agg_i;  // dfac * agg[i]

        // ---- x1 = tanh(a_i + b_j) ----
        float x1[HD];
        const float4* bjp = (const float4*)(g_Bv + j * HD);
#pragma unroll
        for (int q = 0; q < 16; q++) {
            float4 b = bjp[q];
            x1[4 * q + 0] = tanh_fast(sA[4 * q + 0] + b.x);
            x1[4 * q + 1] = tanh_fast(sA[4 * q + 1] + b.y);
            x1[4 * q + 2] = tanh_fast(sA[4 * q + 2] + b.z);
            x1[4 * q + 3] = tanh_fast(sA[4 * q + 3] + b.w);
        }

        // ---- x2 = tanh(Wi2 @ x1 + bi2); isum += (s*x2) @ Wi3T ----
#pragma unroll 2
        for (int r = 0; r < HD; r++) {
            const float4* w = (const float4*)(sWi2 + r * HD);
            float a0 = 0.f, a1 = 0.f, a2 = 0.f, a3 = 0.f;
#pragma unroll
            for (int q = 0; q < 16; q++) {
                float4 wv = w[q];
                a0 += wv.x * x1[4 * q + 0];
                a1 += wv.y * x1[4 * q + 1];
                a2 += wv.z * x1[4 * q + 2];
                a3 += wv.w * x1[4 * q + 3];
            }
            float x2s = s * tanh_fast(sBi2[r] + ((a0 + a1) + (a2 + a3)));
            const float4* w3 = (const float4*)(sWi3T + r * LD);
#pragma unroll
            for (int q = 0; q < 8; q++) {
                float4 wv = w3[q];
                isum[4 * q + 0] += x2s * wv.x;
                isum[4 * q + 1] += x2s * wv.y;
                isum[4 * q + 2] += x2s * wv.z;
                isum[4 * q + 3] += x2s * wv.w;
            }
        }

        // ---- quantum term + bias of k_ij ----
        float pd = ph_i - g_PH[j];
        const float4* cjp = (const float4*)(g_CJ + j * LD);
#pragma unroll
        for (int q = 0; q < 8; q++) {
            float4 c = cjp[q];
            float4 v = hjp[q];  // reload h_j (L1-hot)
            float cz[4] = {c.x, c.y, c.z, c.w};
            float hv[4] = {v.x, v.y, v.z, v.w};
#pragma unroll
            for (int u = 0; u < 4; u++) {
                int l = 4 * q + u;
                float pf = __cosf(pd * sPw[l]);
                float z = sCi[l] + cz[u] + sBc[l];
                float coh = __fdividef(1.0f, 1.0f + __expf(-z));
                // quantum = pf*coh*(-diff) = pf*coh*(hj - hi)
                isum[l] += s * sBi3[l] + pf * coh * (hv[u] - sHi[l]);
            }
        }
    }

    // ---- block reduction of isum across 128 threads ----
#pragma unroll
    for (int l = 0; l < LD; l++) red[tid * 33 + l] = isum[l];
    __syncthreads();
    for (int srd = 64; srd >= 1; srd >>= 1) {
        if (tid < srd) {
#pragma unroll
            for (int l = 0; l < LD; l++)
                red[tid * 33 + l] += red[(tid + srd) * 33 + l];
        }
        __syncthreads();
    }

    if (tid < LD) {
        float v = red[tid];  // row 0 = total isum[l]
        out[i * (LD + 1) + tid] = SELF_SCALE * g_SELF[i * LD + tid] + INT_SCALE * v;
        float av = fabsf(v);
#pragma unroll
        for (int o = 16; o > 0; o >>= 1)
            av += __shfl_down_sync(0xffffffffu, av, o);
        if (tid == 0)
            out[i * (LD + 1) + LD] = 0.1f + 0.05f * av;
    }
}

// ---------------------------------------------------------------------------
extern "C" void kernel_launch(void* const* d_in, const int* in_sizes, int n_in,
                              void* d_out, int out_size)
{
    const float* state   = (const float*)d_in[0];
    const float* Ws1     = (const float*)d_in[1];
    const float* bs1     = (const float*)d_in[2];
    const float* Ws2     = (const float*)d_in[3];
    const float* bs2     = (const float*)d_in[4];
    const float* Ws3     = (const float*)d_in[5];
    const float* bs3     = (const float*)d_in[6];
    const float* Wi1     = (const float*)d_in[7];
    const float* bi1     = (const float*)d_in[8];
    const float* Wi2     = (const float*)d_in[9];
    const float* bi2     = (const float*)d_in[10];
    const float* Wi3     = (const float*)d_in[11];
    const float* bi3     = (const float*)d_in[12];
    const float* phase_w = (const float*)d_in[13];
    const float* Wc      = (const float*)d_in[14];
    const float* bc      = (const float*)d_in[15];
    const float* aggr    = (const float*)d_in[16];
    float* out = (float*)d_out;

    phase1_kernel<<<NB, 64>>>(state, Ws1, bs1, Ws2, bs2, Ws3, bs3,
                              Wi1, bi1, Wc, aggr);
    phase2_kernel<<<NB, 128>>>(Wi2, bi2, Wi3, bi3, phase_w, bc, out);
}

// round 4
// speedup vs baseline: 1.6478x; 1.6478x over previous
#include <cuda_runtime.h>

#define NB 1024
#define LD 32
#define HD 64
#define TJ 128
#define NT 256
#define EPSV 1e-6f
#define SELF_SCALE 0.5f
#define INT_SCALE 0.3f

// Scratch (device globals; no allocation allowed in kernel_launch)
__device__ __align__(16) float g_A[NB * HD];      // a_i            [i][k]
__device__ __align__(16) float g_BvT[HD * NB];    // b_j transposed [k][j]
__device__ __align__(16) float g_CI[NB * LD];     // h @ Wc[:, :L].T
__device__ __align__(16) float g_CJ[NB * LD];     // h @ Wc[:, L:].T
__device__ __align__(16) float g_SELF[NB * LD];   // self_term
__device__ __align__(16) float g_Hh[NB * LD];     // packed h rows
__device__ float g_AG[NB];                        // sigmoid(aggr)
__device__ float g_PH[NB];                        // phases

__device__ __forceinline__ float tanh_fast(float x) {
    // 1 - 2/(exp(2x)+1): exact at saturation, ~1e-7 rel err
    float e = __expf(2.0f * x);
    return 1.0f - __fdividef(2.0f, e + 1.0f);
}

// ---------------------------------------------------------------------------
// Phase 1: per-node precompute. One block (64 threads) per node i.
// ---------------------------------------------------------------------------
__global__ void phase1_kernel(
    const float* __restrict__ state,
    const float* __restrict__ Ws1, const float* __restrict__ bs1,
    const float* __restrict__ Ws2, const float* __restrict__ bs2,
    const float* __restrict__ Ws3, const float* __restrict__ bs3,
    const float* __restrict__ Wi1, const float* __restrict__ bi1,
    const float* __restrict__ Wc,  const float* __restrict__ aggr)
{
    int i = blockIdx.x;
    int t = threadIdx.x;  // 0..63

    __shared__ float sh[LD], st1[HD], st2[HD], sdh[LD];

    if (t < LD) sh[t] = state[i * (LD + 1) + t];
    __syncthreads();

    float acc = bs1[t];
#pragma unroll
    for (int l = 0; l < LD; l++) acc += Ws1[t * LD + l] * sh[l];
    st1[t] = tanhf(acc);
    __syncthreads();

    acc = bs2[t];
#pragma unroll
    for (int k = 0; k < HD; k++) acc += Ws2[t * HD + k] * st1[k];
    st2[t] = tanhf(acc);
    __syncthreads();

    if (t < LD) {
        acc = bs3[t];
#pragma unroll
        for (int k = 0; k < HD; k++) acc += Ws3[t * HD + k] * st2[k];
        sdh[t] = acc;
        g_SELF[i * LD + t] = acc;
        g_Hh[i * LD + t] = sh[t];
    }
    __syncthreads();

    // a_i = h@Wi1[:, :L].T + dh@Wi1[:, 2L:3L].T
    // b_i = h@Wi1[:, L:2L].T + dh@Wi1[:, 3L:].T + bi1
    float a = 0.0f, b = bi1[t];
#pragma unroll
    for (int l = 0; l < LD; l++) {
        float hv = sh[l], dv = sdh[l];
        const float* row = Wi1 + t * (4 * LD);
        a += row[l] * hv + row[2 * LD + l] * dv;
        b += row[LD + l] * hv + row[3 * LD + l] * dv;
    }
    g_A[i * HD + t] = a;
    g_BvT[t * NB + i] = b;   // transposed for coalesced phase-2 reads

    if (t < LD) {
        float ci = 0.0f, cj = 0.0f;
#pragma unroll
        for (int m = 0; m < LD; m++) {
            ci += Wc[t * (2 * LD) + m] * sh[m];
            cj += Wc[t * (2 * LD) + LD + m] * sh[m];
        }
        g_CI[i * LD + t] = ci;
        g_CJ[i * LD + t] = cj;
    }
    if (t == 0) {
        g_AG[i] = 1.0f / (1.0f + expf(-aggr[i]));
        g_PH[i] = state[i * (LD + 1) + LD];
    }
}

// ---------------------------------------------------------------------------
// Phase 2: one block (256 threads) per i; j tiled by 128.
//   stage 1 : x1T[k][j] in SMEM + per-j scale s_j + quantum term
//   stage 2 : register-tiled GEMM y = x1 @ Wi2^T, tanh, fold into colsum[r]
//   finish  : isum_l = colsum @ Wi3[l,:] + ssum*bi3[l] + qsum[l]
// ---------------------------------------------------------------------------
__global__ void __launch_bounds__(NT) phase2_kernel(
    const float* __restrict__ Wi2, const float* __restrict__ bi2,
    const float* __restrict__ Wi3, const float* __restrict__ bi3,
    const float* __restrict__ phase_w, const float* __restrict__ bc,
    float* __restrict__ out)
{
    __shared__ __align__(16) float sWi2T[HD * HD];   // [k][r]  16 KB
    __shared__ __align__(16) float sX1T[HD][TJ];     // [k][j]  32 KB
    __shared__ float sS[TJ];
    __shared__ float sA[HD], sBi2[HD];
    __shared__ float sHi[LD], sCi[LD], sPw[LD], sBc[LD];
    __shared__ float sColRed[16][HD];                // 4 KB
    __shared__ float sQRed[8][LD];
    __shared__ float sSsumRed[8];
    __shared__ float sColsum[HD];
    __shared__ float sSsum;

    int i = blockIdx.x;
    int tid = threadIdx.x;
    int lane = tid & 31;
    int warp = tid >> 5;

    for (int idx = tid; idx < HD * HD; idx += NT) {
        int k = idx >> 6, r = idx & 63;
        sWi2T[idx] = Wi2[r * HD + k];          // sWi2T[k][r]
    }
    if (tid < HD) { sA[tid] = g_A[i * HD + tid]; sBi2[tid] = bi2[tid]; }
    if (tid < LD) {
        sHi[tid] = g_Hh[i * LD + tid];
        sCi[tid] = g_CI[i * LD + tid];
        sPw[tid] = phase_w[tid];
        sBc[tid] = bc[tid];
    }
    __syncthreads();

    float agg_i = g_AG[i];
    float ph_i  = g_PH[i];
    float hi_l = sHi[lane], ci_l = sCi[lane], pw_l = sPw[lane], bc_l = sBc[lane];

    float colsum0 = 0.f, colsum1 = 0.f, colsum2 = 0.f, colsum3 = 0.f;
    float qacc = 0.f;
    float ssum = 0.f;

    int jj1 = tid & 127;           // stage-1 j index
    int kh  = (tid >> 7) * 32;     // stage-1 k half
    int jt = tid & 15, rt = tid >> 4;
    int jb = jt * 8, rb = rt * 4;

    for (int t = 0; t < 8; t++) {
        int j0 = t * TJ;

        // ---- stage 1a: x1T[k][j] = tanh(a_i[k] + b_j[k]) ----
#pragma unroll
        for (int u = 0; u < 32; u++) {
            float b = g_BvT[(kh + u) * NB + j0 + jj1];   // coalesced
            sX1T[kh + u][jj1] = tanh_fast(sA[kh + u] + b);
        }

        // ---- stage 1b: dist + quantum. One warp per 16 j, lane = l ----
#pragma unroll 1
        for (int v = 0; v < 16; v++) {
            int j = j0 + warp * 16 + v;
            float hj = g_Hh[j * LD + lane];              // coalesced
            float e = hj - hi_l;
            float d2 = e * e;
#pragma unroll
            for (int o = 16; o > 0; o >>= 1)
                d2 += __shfl_xor_sync(0xffffffffu, d2, o);
            float s = fminf(__fdividef(1.0f, sqrtf(d2) + EPSV), 2.0f) * agg_i;
            if (j == i) s = 0.0f;
            if (lane == 0) { sS[warp * 16 + v] = s; ssum += s; }

            float pd = ph_i - g_PH[j];
            float cj = g_CJ[j * LD + lane];              // coalesced
            float pf = __cosf(pd * pw_l);
            float z  = ci_l + cj + bc_l;
            float coh = __fdividef(1.0f, 1.0f + __expf(-z));
            qacc += pf * coh * e;                        // pf*coh*(hj - hi)
        }
        __syncthreads();

        // ---- stage 2: GEMM micro-tile 8j x 4r per thread ----
        float acc[8][4];
#pragma unroll
        for (int u = 0; u < 8; u++)
#pragma unroll
            for (int v = 0; v < 4; v++) acc[u][v] = 0.0f;

#pragma unroll 8
        for (int k = 0; k < HD; k++) {
            float4 xa = *(const float4*)&sX1T[k][jb];
            float4 xb = *(const float4*)&sX1T[k][jb + 4];
            float4 w  = *(const float4*)&sWi2T[k * HD + rb];
            float xv[8] = {xa.x, xa.y, xa.z, xa.w, xb.x, xb.y, xb.z, xb.w};
            float wv[4] = {w.x, w.y, w.z, w.w};
#pragma unroll
            for (int u = 0; u < 8; u++)
#pragma unroll
                for (int v = 0; v < 4; v++)
                    acc[u][v] += xv[u] * wv[v];
        }

        // epilogue: x2 = tanh(acc + bi2), weight by s_j, fold into colsum[r]
        float b0 = sBi2[rb], b1 = sBi2[rb + 1], b2 = sBi2[rb + 2], b3 = sBi2[rb + 3];
#pragma unroll
        for (int u = 0; u < 8; u++) {
            float su = sS[jb + u];
            colsum0 += su * tanh_fast(acc[u][0] + b0);
            colsum1 += su * tanh_fast(acc[u][1] + b1);
            colsum2 += su * tanh_fast(acc[u][2] + b2);
            colsum3 += su * tanh_fast(acc[u][3] + b3);
        }
        __syncthreads();   // protect sX1T/sS before next tile overwrites
    }

    // ---- reductions ----
    sColRed[jt][rb + 0] = colsum0;
    sColRed[jt][rb + 1] = colsum1;
    sColRed[jt][rb + 2] = colsum2;
    sColRed[jt][rb + 3] = colsum3;
    sQRed[warp][lane] = qacc;                 // lane = l (32 wide)
    if (lane == 0) sSsumRed[warp] = ssum;
    __syncthreads();

    if (tid < HD) {
        float c = 0.0f;
#pragma unroll
        for (int u = 0; u < 16; u++) c += sColRed[u][tid];
        sColsum[tid] = c;
    }
    if (tid == 0) {
        float sst = 0.0f;
#pragma unroll
        for (int u = 0; u < 8; u++) sst += sSsumRed[u];
        sSsum = sst;
    }
    __syncthreads();

    if (tid < LD) {
        float q = 0.0f;
#pragma unroll
        for (int u = 0; u < 8; u++) q += sQRed[u][tid];
        float kv = sSsum * bi3[tid];
#pragma unroll
        for (int r = 0; r < HD; r++) kv += sColsum[r] * Wi3[tid * HD + r];
        float v = kv + q;                               // isum[l]
        out[i * (LD + 1) + tid] = SELF_SCALE * g_SELF[i * LD + tid] + INT_SCALE * v;
        float av = fabsf(v);
#pragma unroll
        for (int o = 16; o > 0; o >>= 1)
            av += __shfl_down_sync(0xffffffffu, av, o);
        if (tid == 0)
            out[i * (LD + 1) + LD] = 0.1f + 0.05f * av;
    }
}

// ---------------------------------------------------------------------------
extern "C" void kernel_launch(void* const* d_in, const int* in_sizes, int n_in,
                              void* d_out, int out_size)
{
    const float* state   = (const float*)d_in[0];
    const float* Ws1     = (const float*)d_in[1];
    const float* bs1     = (const float*)d_in[2];
    const float* Ws2     = (const float*)d_in[3];
    const float* bs2     = (const float*)d_in[4];
    const float* Ws3     = (const float*)d_in[5];
    const float* bs3     = (const float*)d_in[6];
    const float* Wi1     = (const float*)d_in[7];
    const float* bi1     = (const float*)d_in[8];
    const float* Wi2     = (const float*)d_in[9];
    const float* bi2     = (const float*)d_in[10];
    const float* Wi3     = (const float*)d_in[11];
    const float* bi3     = (const float*)d_in[12];
    const float* phase_w = (const float*)d_in[13];
    const float* Wc      = (const float*)d_in[14];
    const float* bc      = (const float*)d_in[15];
    const float* aggr    = (const float*)d_in[16];
    float* out = (float*)d_out;

    phase1_kernel<<<NB, 64>>>(state, Ws1, bs1, Ws2, bs2, Ws3, bs3,
                              Wi1, bi1, Wc, aggr);
    phase2_kernel<<<NB, NT>>>(Wi2, bi2, Wi3, bi3, phase_w, bc, out);
}